// round 16
// baseline (speedup 1.0000x reference)
#include <cuda_runtime.h>
#include <cuda_bf16.h>
#include <cstdint>

// ---------------------------------------------------------------- constants
#define NB 8
#define SEQ 1024
#define DIN 1280
#define RK 64
#define DOUT 1280
#define DOWN_SZ (RK * DIN)        // 81920
#define UP_SZ (DOUT * RK)         // 81920
#define EMB_STRIDE (DOWN_SZ + UP_SZ)
#define H_ELEMS (NB * SEQ * RK)   // 524288
#define KSPLIT 2
#define KHALF (DIN / KSPLIT)      // 640

// ------------------------------------------------------------ device scratch
__device__ float         g_hpart[KSPLIT * H_ELEMS]; // split-K fp32 partials (4 MB)
__device__ __align__(16) __nv_bfloat16 g_h_hi[H_ELEMS];
__device__ __align__(16) __nv_bfloat16 g_h_lo[H_ELEMS];
__device__ __align__(16) __nv_bfloat16 g_w_hi[NB * EMB_STRIDE];
__device__ __align__(16) __nv_bfloat16 g_w_lo[NB * EMB_STRIDE];

// ---------------------------------------------------------------- helpers
__device__ __forceinline__ uint32_t s2u(const void* p) {
    uint32_t a;
    asm("{ .reg .u64 t; cvta.to.shared.u64 t, %1; cvt.u32.u64 %0, t; }" : "=r"(a) : "l"(p));
    return a;
}
__device__ __forceinline__ void split2(float x, uint16_t& h, uint16_t& l) {
    __nv_bfloat16 hb = __float2bfloat16(x);
    __nv_bfloat16 lb = __float2bfloat16(x - __bfloat162float(hb));
    h = *(uint16_t*)&hb; l = *(uint16_t*)&lb;
}
__device__ __forceinline__ uint32_t pk(uint16_t a, uint16_t b) {
    return (uint32_t)a | ((uint32_t)b << 16);
}
__device__ __forceinline__ void split8(float4 v0, float4 v1, uint4& hh, uint4& ll) {
    uint16_t h[8], l[8];
    split2(v0.x, h[0], l[0]); split2(v0.y, h[1], l[1]);
    split2(v0.z, h[2], l[2]); split2(v0.w, h[3], l[3]);
    split2(v1.x, h[4], l[4]); split2(v1.y, h[5], l[5]);
    split2(v1.z, h[6], l[6]); split2(v1.w, h[7], l[7]);
    hh = make_uint4(pk(h[0],h[1]), pk(h[2],h[3]), pk(h[4],h[5]), pk(h[6],h[7]));
    ll = make_uint4(pk(l[0],l[1]), pk(l[2],l[3]), pk(l[4],l[5]), pk(l[6],l[7]));
}
__device__ __forceinline__ void ldsm4(uint32_t r[4], uint32_t addr) {
    asm volatile("ldmatrix.sync.aligned.m8n8.x4.shared.b16 {%0,%1,%2,%3}, [%4];"
        : "=r"(r[0]), "=r"(r[1]), "=r"(r[2]), "=r"(r[3]) : "r"(addr));
}
__device__ __forceinline__ void mma_bf16(float d[4], const uint32_t a[4],
                                         uint32_t b0, uint32_t b1) {
    asm volatile(
        "mma.sync.aligned.m16n8k16.row.col.f32.bf16.bf16.f32 "
        "{%0,%1,%2,%3}, {%4,%5,%6,%7}, {%8,%9}, {%0,%1,%2,%3};"
        : "+f"(d[0]), "+f"(d[1]), "+f"(d[2]), "+f"(d[3])
        : "r"(a[0]), "r"(a[1]), "r"(a[2]), "r"(a[3]), "r"(b0), "r"(b1));
}

// ---------------------------------------------------------------------------
// prep: split embed (fp32) into bf16 hi/lo. 4 independent chunks/thread.
// ---------------------------------------------------------------------------
#define PREP_T (320 * 256)
__global__ __launch_bounds__(256) void prep_kernel(const float* __restrict__ embed)
{
    const size_t t = (size_t)blockIdx.x * 256 + threadIdx.x;
#pragma unroll
    for (int q = 0; q < 4; q++) {
        const size_t i = (t + (size_t)q * PREP_T) * 4;
        float4 v = *(const float4*)(embed + i);
        uint16_t h0, l0, h1, l1, h2, l2, h3, l3;
        split2(v.x, h0, l0); split2(v.y, h1, l1);
        split2(v.z, h2, l2); split2(v.w, h3, l3);
        *(uint2*)(g_w_hi + i) = make_uint2(pk(h0, h1), pk(h2, h3));
        *(uint2*)(g_w_lo + i) = make_uint2(pk(l0, l1), pk(l2, l3));
    }
}

// ---------------------------------------------------------------------------
// down: h_part[ks] = x[:,ksK:+K] @ Wdown[:,ksK:+K]^T, bf16x3 mma.sync.
// CTA 64x64, split-K=2 (10 K-chunks of 64). 8 warps, tile 32x16.
// Register-prefetch pipeline (proven R12 version, unchanged).
// ---------------------------------------------------------------------------
#define DST 72              // smem row stride in bf16 elems (conflict-free)
__global__ __launch_bounds__(256) void down_kernel(const float* __restrict__ x)
{
    __shared__ __align__(16) uint16_t sm[4 * 64 * DST];
    uint16_t* AH = sm;
    uint16_t* AL = sm + 64 * DST;
    uint16_t* BH = sm + 2 * 64 * DST;
    uint16_t* BL = sm + 3 * 64 * DST;

    const int tid = threadIdx.x, lane = tid & 31, wid = tid >> 5;
    const int ks = blockIdx.x, mt = blockIdx.y, b = blockIdx.z;
    const int kbeg = ks * KHALF;

    const float* A = x + ((size_t)b * SEQ + (size_t)mt * 64) * DIN;
    const __nv_bfloat16* WH = g_w_hi + (size_t)b * EMB_STRIDE;
    const __nv_bfloat16* WL = g_w_lo + (size_t)b * EMB_STRIDE;
    float* C = g_hpart + (size_t)ks * H_ELEMS + ((size_t)b * SEQ + (size_t)mt * 64) * RK;

    const int lrow = tid >> 2, lcs = (tid & 3) * 16;
    const int wm = (wid & 1) * 32, wn = (wid >> 1) * 16;

    const uint32_t ahb = s2u(AH), alb = s2u(AL), bhb = s2u(BH), blb = s2u(BL);
    const int aoff = (lane & 15) * DST + (lane >> 4) * 8;
    const int boff = (((lane >> 3) & 1) * 8 + (lane & 7)) * DST + (lane >> 4) * 8;

    float acc[2][2][4];
#pragma unroll
    for (int i = 0; i < 2; i++)
#pragma unroll
        for (int j = 0; j < 2; j++)
#pragma unroll
            for (int q = 0; q < 4; q++) acc[i][j][q] = 0.f;

    float4 xv0, xv1, xv2, xv3;
    uint4 whv0, whv1, wlv0, wlv1;
    {
        const float* ap = A + (size_t)lrow * DIN + kbeg + lcs;
        xv0 = *(const float4*)ap;       xv1 = *(const float4*)(ap + 4);
        xv2 = *(const float4*)(ap + 8); xv3 = *(const float4*)(ap + 12);
        const __nv_bfloat16* wp = WH + (size_t)lrow * DIN + kbeg + lcs;
        whv0 = *(const uint4*)wp; whv1 = *(const uint4*)(wp + 8);
        wp = WL + (size_t)lrow * DIN + kbeg + lcs;
        wlv0 = *(const uint4*)wp; wlv1 = *(const uint4*)(wp + 8);
    }

    for (int ch = 0; ch < KHALF / 64; ch++) {
        if (ch) __syncthreads();
        uint4 hh0, ll0, hh1, ll1;
        split8(xv0, xv1, hh0, ll0);
        split8(xv2, xv3, hh1, ll1);
        {
            uint16_t* p = AH + lrow * DST + lcs;
            *(uint4*)p = hh0; *(uint4*)(p + 8) = hh1;
            p = AL + lrow * DST + lcs;
            *(uint4*)p = ll0; *(uint4*)(p + 8) = ll1;
            p = BH + lrow * DST + lcs;
            *(uint4*)p = whv0; *(uint4*)(p + 8) = whv1;
            p = BL + lrow * DST + lcs;
            *(uint4*)p = wlv0; *(uint4*)(p + 8) = wlv1;
        }
        __syncthreads();

        if (ch + 1 < KHALF / 64) {
            const int kc = kbeg + (ch + 1) * 64;
            const float* ap = A + (size_t)lrow * DIN + kc + lcs;
            xv0 = *(const float4*)ap;       xv1 = *(const float4*)(ap + 4);
            xv2 = *(const float4*)(ap + 8); xv3 = *(const float4*)(ap + 12);
            const __nv_bfloat16* wp = WH + (size_t)lrow * DIN + kc + lcs;
            whv0 = *(const uint4*)wp; whv1 = *(const uint4*)(wp + 8);
            wp = WL + (size_t)lrow * DIN + kc + lcs;
            wlv0 = *(const uint4*)wp; wlv1 = *(const uint4*)(wp + 8);
        }

#pragma unroll
        for (int ks2 = 0; ks2 < 4; ks2++) {
            const int kb = ks2 * 16;
            uint32_t ah0[4], ah1[4], al0[4], al1[4], bh[4], bl[4];
            ldsm4(ah0, ahb + (uint32_t)(wm * DST + kb + aoff) * 2);
            ldsm4(ah1, ahb + (uint32_t)((wm + 16) * DST + kb + aoff) * 2);
            ldsm4(al0, alb + (uint32_t)(wm * DST + kb + aoff) * 2);
            ldsm4(al1, alb + (uint32_t)((wm + 16) * DST + kb + aoff) * 2);
            ldsm4(bh,  bhb + (uint32_t)(wn * DST + kb + boff) * 2);
            ldsm4(bl,  blb + (uint32_t)(wn * DST + kb + boff) * 2);
            mma_bf16(acc[0][0], ah0, bh[0], bh[2]);
            mma_bf16(acc[0][0], ah0, bl[0], bl[2]);
            mma_bf16(acc[0][0], al0, bh[0], bh[2]);
            mma_bf16(acc[0][1], ah0, bh[1], bh[3]);
            mma_bf16(acc[0][1], ah0, bl[1], bl[3]);
            mma_bf16(acc[0][1], al0, bh[1], bh[3]);
            mma_bf16(acc[1][0], ah1, bh[0], bh[2]);
            mma_bf16(acc[1][0], ah1, bl[0], bl[2]);
            mma_bf16(acc[1][0], al1, bh[0], bh[2]);
            mma_bf16(acc[1][1], ah1, bh[1], bh[3]);
            mma_bf16(acc[1][1], ah1, bl[1], bl[3]);
            mma_bf16(acc[1][1], al1, bh[1], bh[3]);
        }
    }

    const int er = lane >> 2, ec = (lane & 3) * 2;
#pragma unroll
    for (int mf = 0; mf < 2; mf++)
#pragma unroll
        for (int nf = 0; nf < 2; nf++) {
            float* c0 = C + (size_t)(wm + mf * 16 + er) * RK + wn + nf * 8 + ec;
            *(float2*)c0            = make_float2(acc[mf][nf][0], acc[mf][nf][1]);
            *(float2*)(c0 + 8 * RK) = make_float2(acc[mf][nf][2], acc[mf][nf][3]);
        }
}

// ---------------------------------------------------------------------------
// reduce: h = part0 + part1, emitted once as bf16 hi/lo.
// ---------------------------------------------------------------------------
__global__ __launch_bounds__(256) void reduce_kernel()
{
    const size_t i = ((size_t)blockIdx.x * 256 + threadIdx.x) * 4;
    float4 a = *(const float4*)(g_hpart + i);
    float4 c = *(const float4*)(g_hpart + (size_t)H_ELEMS + i);
    a.x += c.x; a.y += c.y; a.z += c.z; a.w += c.w;
    uint16_t h0, l0, h1, l1, h2, l2, h3, l3;
    split2(a.x, h0, l0); split2(a.y, h1, l1);
    split2(a.z, h2, l2); split2(a.w, h3, l3);
    *(uint2*)(g_h_hi + i) = make_uint2(pk(h0, h1), pk(h2, h3));
    *(uint2*)(g_h_lo + i) = make_uint2(pk(l0, l1), pk(l2, l3));
}

// ---------------------------------------------------------------------------
// up: out = h @ Wup^T, bf16x3 mma.sync.  OCCUPANCY-TUNED: CTA = 64x128 tile
// (smem 55.3 KB, small acc) with 3 CTAs/SM forced -> 24 warps/SM resident.
// grid = 10 x 16 x 8 = 1280 CTAs. 8 warps, warp tile 32x32.
// ---------------------------------------------------------------------------
#define UPA (64 * DST)            // elems per A array
#define UPB (128 * DST)           // elems per B array
#define UP_SMEM ((2 * UPA + 2 * UPB) * 2)   // 55296 bytes
__global__ __launch_bounds__(256, 3) void up_kernel(float* __restrict__ out)
{
    extern __shared__ __align__(16) uint16_t usm[];
    uint16_t* AH = usm;                    // 64 x DST
    uint16_t* AL = usm + UPA;
    uint16_t* BH = usm + 2 * UPA;          // 128 x DST
    uint16_t* BL = usm + 2 * UPA + UPB;

    const int tid = threadIdx.x, lane = tid & 31, wid = tid >> 5;
    const int nt = blockIdx.x, mt = blockIdx.y, b = blockIdx.z;

    const __nv_bfloat16* hH = g_h_hi + ((size_t)b * SEQ + (size_t)mt * 64) * RK;
    const __nv_bfloat16* hL = g_h_lo + ((size_t)b * SEQ + (size_t)mt * 64) * RK;
    const __nv_bfloat16* WH = g_w_hi + (size_t)b * EMB_STRIDE + DOWN_SZ + (size_t)nt * 128 * RK;
    const __nv_bfloat16* WL = g_w_lo + (size_t)b * EMB_STRIDE + DOWN_SZ + (size_t)nt * 128 * RK;
    float* O = out + ((size_t)b * SEQ + (size_t)mt * 64) * DOUT + (size_t)nt * 128;

    // loaders: A 64 rows x 64 cols (4 thr/row, 16-col segs); B 128 rows (2 thr/row, 32-col segs)
    {
        const int arow = tid >> 2, acs = (tid & 3) * 16;
        const __nv_bfloat16* ah = hH + (size_t)arow * RK + acs;
        const __nv_bfloat16* al = hL + (size_t)arow * RK + acs;
        *(uint4*)(AH + arow * DST + acs)     = *(const uint4*)ah;
        *(uint4*)(AH + arow * DST + acs + 8) = *(const uint4*)(ah + 8);
        *(uint4*)(AL + arow * DST + acs)     = *(const uint4*)al;
        *(uint4*)(AL + arow * DST + acs + 8) = *(const uint4*)(al + 8);

        const int brow = tid >> 1, bcs = (tid & 1) * 32;
        const __nv_bfloat16* wh = WH + (size_t)brow * RK + bcs;
        const __nv_bfloat16* wl = WL + (size_t)brow * RK + bcs;
#pragma unroll
        for (int j = 0; j < 4; j++) {
            *(uint4*)(BH + brow * DST + bcs + j * 8) = *(const uint4*)(wh + j * 8);
            *(uint4*)(BL + brow * DST + bcs + j * 8) = *(const uint4*)(wl + j * 8);
        }
    }
    __syncthreads();

    // warp tiling: 2 (M) x 4 (N); warp tile 32 x 32
    const int wm = (wid & 1) * 32, wn = (wid >> 1) * 32;
    const uint32_t ahb = s2u(AH), alb = s2u(AL), bhb = s2u(BH), blb = s2u(BL);
    const int aoff = (lane & 15) * DST + (lane >> 4) * 8;
    const int boff = (((lane >> 3) & 1) * 8 + (lane & 7)) * DST + (lane >> 4) * 8;

    float acc[2][4][4];
#pragma unroll
    for (int i = 0; i < 2; i++)
#pragma unroll
        for (int j = 0; j < 4; j++)
#pragma unroll
            for (int q = 0; q < 4; q++) acc[i][j][q] = 0.f;

#pragma unroll
    for (int ks = 0; ks < 4; ks++) {
        const int kb = ks * 16;
        uint32_t ah[2][4], al[2][4];
        ldsm4(ah[0], ahb + (uint32_t)(wm * DST + kb + aoff) * 2);
        ldsm4(ah[1], ahb + (uint32_t)((wm + 16) * DST + kb + aoff) * 2);
        ldsm4(al[0], alb + (uint32_t)(wm * DST + kb + aoff) * 2);
        ldsm4(al[1], alb + (uint32_t)((wm + 16) * DST + kb + aoff) * 2);
        uint32_t bh[2][4], bl[2][4];   // pair p covers nfrags 2p, 2p+1
#pragma unroll
        for (int p = 0; p < 2; p++) {
            ldsm4(bh[p], bhb + (uint32_t)((wn + p * 16) * DST + kb + boff) * 2);
            ldsm4(bl[p], blb + (uint32_t)((wn + p * 16) * DST + kb + boff) * 2);
        }
#pragma unroll
        for (int mf = 0; mf < 2; mf++)
#pragma unroll
            for (int p = 0; p < 2; p++) {
                mma_bf16(acc[mf][2*p],   ah[mf], bh[p][0], bh[p][2]);
                mma_bf16(acc[mf][2*p],   ah[mf], bl[p][0], bl[p][2]);
                mma_bf16(acc[mf][2*p],   al[mf], bh[p][0], bh[p][2]);
                mma_bf16(acc[mf][2*p+1], ah[mf], bh[p][1], bh[p][3]);
                mma_bf16(acc[mf][2*p+1], ah[mf], bl[p][1], bl[p][3]);
                mma_bf16(acc[mf][2*p+1], al[mf], bh[p][1], bh[p][3]);
            }
    }

    // epilogue: direct fp32 stores
    const int er = lane >> 2, ec = (lane & 3) * 2;
#pragma unroll
    for (int mf = 0; mf < 2; mf++)
#pragma unroll
        for (int nf = 0; nf < 4; nf++) {
            float* c0 = O + (size_t)(wm + mf * 16 + er) * DOUT + wn + nf * 8 + ec;
            *(float2*)c0              = make_float2(acc[mf][nf][0], acc[mf][nf][1]);
            *(float2*)(c0 + 8 * DOUT) = make_float2(acc[mf][nf][2], acc[mf][nf][3]);
        }
}

// ---------------------------------------------------------------------------
extern "C" void kernel_launch(void* const* d_in, const int* in_sizes, int n_in,
                              void* d_out, int out_size)
{
    const float* x     = (const float*)d_in[0];   // [B, S, D_IN] fp32
    const float* embed = (const float*)d_in[1];   // [B, DOWN+UP] fp32
    float*       out   = (float*)d_out;           // [B, S, D_OUT] fp32
    (void)in_sizes; (void)n_in; (void)out_size;

    cudaFuncSetAttribute(up_kernel, cudaFuncAttributeMaxDynamicSharedMemorySize, UP_SMEM);

    // 1) split embed into bf16 hi/lo
    prep_kernel<<<320, 256>>>(embed);
    // 2) down GEMM split-K=2: grid 2 x 16 x 8 = 256 CTAs
    down_kernel<<<dim3(KSPLIT, SEQ / 64, NB), 256>>>(x);
    // 3) reduce partials -> bf16 hi/lo h
    reduce_kernel<<<H_ELEMS / 4 / 256, 256>>>();
    // 4) up GEMM: grid 10 x 16 x 8 = 1280 CTAs (64x128 tiles, 3 CTAs/SM)
    up_kernel<<<dim3(DOUT / 128, SEQ / 64, NB), 256, UP_SMEM>>>(out);
}